// round 9
// baseline (speedup 1.0000x reference)
#include <cuda_runtime.h>
#include <cuda_fp16.h>

#define D      128
#define NMAX   100000
#define NP     (NMAX + 1)
#define EMAX   1600000
#define SCAN_B 1024
#define NBLK   ((NP + SCAN_B - 1) / SCAN_B)   // 98

#define GEMM_BLOCKS ((NMAX + 63) / 64)        // 1563 (64-row tiles, 2 blk/SM)
#define CNT_BLOCKS  1184                      // tail blocks of the gemm launch

// Scratch (device globals — no allocations allowed)
__device__ __half g_X0h[(size_t)NMAX * D];    // notes @ w in fp16 (25.6 MB)
__device__ uint4  g_wfrag[8 * 16 * 32];       // B fragments: {bh0,bh1,bl0,bl1}
__device__ int    g_offs[NP];
__device__ int2   g_csr[EMAX];                // packed {dst, w_bits}

// Zeroed once per launch by a single cudaMemsetAsync graph node
struct ScanScratch {
    int deg[NP];
    int flag[NBLK];    // 0 none, 1 aggregate, 2 inclusive
    int agg[NBLK];
    int inc[NBLK];
};
__device__ ScanScratch g_ss;

static __device__ __forceinline__ unsigned pack_bf16x2(float f0, float f1) {
    unsigned h;
    asm("cvt.rn.bf16x2.f32 %0, %1, %2;" : "=r"(h) : "f"(f1), "f"(f0));
    return h;
}

// ---------------------------------------------------------------------------
// Prep: build w fragments in mma register order (16 blocks, tiny).
// ---------------------------------------------------------------------------
__global__ void prep_kernel(const float* __restrict__ w) {
    int f = blockIdx.x * 256 + threadIdx.x;   // 0..4095
    int lane = f & 31;
    int nt   = (f >> 5) & 15;
    int ks   = f >> 9;
    int g  = lane >> 2;
    int tq = lane & 3;
    int n  = nt * 8 + g;
    int k0 = ks * 16 + 2 * tq;
    int k1 = k0 + 8;

    float a0 = w[(k0)     * D + n];
    float a1 = w[(k0 + 1) * D + n];
    float c0 = w[(k1)     * D + n];
    float c1 = w[(k1 + 1) * D + n];

    unsigned bh0 = pack_bf16x2(a0, a1);
    unsigned bh1 = pack_bf16x2(c0, c1);
    float h0 = __uint_as_float(bh0 << 16);
    float h1 = __uint_as_float(bh0 & 0xffff0000u);
    float h2 = __uint_as_float(bh1 << 16);
    float h3 = __uint_as_float(bh1 & 0xffff0000u);
    unsigned bl0 = pack_bf16x2(a0 - h0, a1 - h1);
    unsigned bl1 = pack_bf16x2(c0 - h2, c1 - h3);

    g_wfrag[f] = make_uint4(bh0, bh1, bl0, bl1);
}

// ---------------------------------------------------------------------------
// Fused tensor-core GEMM + degree count (count as tail blocks — they run in
// the trailing wave of the same launch: zero overhead, no cross-stream L2
// contention). GEMM: 2x2 warp tiling — block = 4 warps, tile 64x128;
// warp = 32 rows x 64 cols; each B-fragment read feeds 6 MMAs.
// ---------------------------------------------------------------------------
#define SN_PITCH 132

__global__ void __launch_bounds__(128) gemm_count_kernel(
        const float* __restrict__ notes,
        const int*   __restrict__ esrc,
        float* __restrict__ out, int N, int garment, int E) {
    if (blockIdx.x >= GEMM_BLOCKS) {
        // ---- degree count path (tail wave) ----
        int tidg = (blockIdx.x - GEMM_BLOCKS) * 128 + threadIdx.x;
        int nth  = CNT_BLOCKS * 128;
        int E4   = E >> 2;
        const int4* s4 = (const int4*)esrc;
        for (int i = tidg; i < E4; i += nth) {
            int4 s = s4[i];
            atomicAdd(&g_ss.deg[s.x], 1);
            atomicAdd(&g_ss.deg[s.y], 1);
            atomicAdd(&g_ss.deg[s.z], 1);
            atomicAdd(&g_ss.deg[s.w], 1);
        }
        if (tidg == 0)
            for (int e = E4 << 2; e < E; e++) atomicAdd(&g_ss.deg[esrc[e]], 1);
        return;
    }

    extern __shared__ char smem_raw[];
    float* s_n  = (float*)smem_raw;                           // [64][132] f32
    uint4* s_bf = (uint4*)(smem_raw + 64 * SN_PITCH * 4);     // [8*16*32]

    const int t    = threadIdx.x;
    const int warp = t >> 5;
    const int lane = t & 31;
    const int wm   = warp & 1;         // M half (rows wm*32 .. +31)
    const int wn   = warp >> 1;        // N half (cols wn*64 .. +63)
    const int g    = lane >> 2;
    const int tq   = lane & 3;
    const int row0 = blockIdx.x * 64;

    #pragma unroll
    for (int i = t; i < 4096; i += 128) s_bf[i] = g_wfrag[i];

    const float4* n4 = (const float4*)notes;
    #pragma unroll
    for (int i = t; i < 2048; i += 128) {
        int r = i >> 5, c4 = i & 31;
        int gr = row0 + r;
        float4 v = make_float4(0.f, 0.f, 0.f, 0.f);
        if (gr < N) v = n4[(size_t)gr * 32 + c4];
        *(float4*)&s_n[r * SN_PITCH + c4 * 4] = v;
    }
    __syncthreads();

    float acc[8][8];   // [nt][h*4 + j]
    #pragma unroll
    for (int nt = 0; nt < 8; nt++)
        #pragma unroll
        for (int j = 0; j < 8; j++) acc[nt][j] = 0.f;

    #pragma unroll
    for (int ks = 0; ks < 8; ks++) {
        // A fragments for both 16-row halves: f32 -> bf16 hi/lo on the fly
        unsigned ahi[2][4], alo[2][4];
        #pragma unroll
        for (int h = 0; h < 2; h++) {
            #pragma unroll
            for (int i = 0; i < 4; i++) {
                int r = wm * 32 + h * 16 + g + (i & 1) * 8;
                int k = ks * 16 + tq * 2 + (i >> 1) * 8;
                float2 f = *(const float2*)&s_n[r * SN_PITCH + k];
                unsigned hh = pack_bf16x2(f.x, f.y);
                float hx = __uint_as_float(hh << 16);
                float hy = __uint_as_float(hh & 0xffff0000u);
                ahi[h][i] = hh;
                alo[h][i] = pack_bf16x2(f.x - hx, f.y - hy);
            }
        }
        const uint4* bf = &s_bf[(ks * 16 + wn * 8) * 32 + lane];
        #pragma unroll
        for (int nt = 0; nt < 8; nt++) {
            uint4 f = bf[nt * 32];
            #pragma unroll
            for (int h = 0; h < 2; h++) {
                float* a = &acc[nt][h * 4];
                asm volatile(
                    "mma.sync.aligned.m16n8k16.row.col.f32.bf16.bf16.f32 "
                    "{%0,%1,%2,%3}, {%4,%5,%6,%7}, {%8,%9}, {%0,%1,%2,%3};"
                    : "+f"(a[0]), "+f"(a[1]), "+f"(a[2]), "+f"(a[3])
                    : "r"(ahi[h][0]), "r"(ahi[h][1]), "r"(ahi[h][2]), "r"(ahi[h][3]),
                      "r"(f.x), "r"(f.y));
                asm volatile(
                    "mma.sync.aligned.m16n8k16.row.col.f32.bf16.bf16.f32 "
                    "{%0,%1,%2,%3}, {%4,%5,%6,%7}, {%8,%9}, {%0,%1,%2,%3};"
                    : "+f"(a[0]), "+f"(a[1]), "+f"(a[2]), "+f"(a[3])
                    : "r"(ahi[h][0]), "r"(ahi[h][1]), "r"(ahi[h][2]), "r"(ahi[h][3]),
                      "r"(f.z), "r"(f.w));
                asm volatile(
                    "mma.sync.aligned.m16n8k16.row.col.f32.bf16.bf16.f32 "
                    "{%0,%1,%2,%3}, {%4,%5,%6,%7}, {%8,%9}, {%0,%1,%2,%3};"
                    : "+f"(a[0]), "+f"(a[1]), "+f"(a[2]), "+f"(a[3])
                    : "r"(alo[h][0]), "r"(alo[h][1]), "r"(alo[h][2]), "r"(alo[h][3]),
                      "r"(f.x), "r"(f.y));
            }
        }
    }

    // Epilogue: X0 -> fp16 scratch; rows >= garment -> fp32 output tail.
    #pragma unroll
    for (int h = 0; h < 2; h++) {
        const int r0 = row0 + wm * 32 + h * 16 + g;
        const int r1 = r0 + 8;
        #pragma unroll
        for (int nt = 0; nt < 8; nt++) {
            int col = wn * 64 + nt * 8 + tq * 2;
            if (r0 < N) {
                *(half2*)&g_X0h[(size_t)r0 * D + col] =
                    __floats2half2_rn(acc[nt][h*4+0], acc[nt][h*4+1]);
                if (r0 >= garment)
                    *(float2*)&out[(size_t)(N + r0 - garment) * D + col] =
                        make_float2(acc[nt][h*4+0], acc[nt][h*4+1]);
            }
            if (r1 < N) {
                *(half2*)&g_X0h[(size_t)r1 * D + col] =
                    __floats2half2_rn(acc[nt][h*4+2], acc[nt][h*4+3]);
                if (r1 >= garment)
                    *(float2*)&out[(size_t)(N + r1 - garment) * D + col] =
                        make_float2(acc[nt][h*4+2], acc[nt][h*4+3]);
            }
        }
    }
}

// ---------------------------------------------------------------------------
// Single-pass exclusive scan (decoupled lookback), 98 blocks x 1024
// ---------------------------------------------------------------------------
__global__ void scan_kernel() {
    __shared__ int wsum[32];
    __shared__ int s_total;
    __shared__ int s_prefix;
    const int t = threadIdx.x, lane = t & 31, warp = t >> 5;
    const int bid = blockIdx.x;
    const int i = bid * SCAN_B + t;
    int v = (i < NP) ? g_ss.deg[i] : 0;

    int x = v;
    #pragma unroll
    for (int off = 1; off < 32; off <<= 1) {
        int y = __shfl_up_sync(0xffffffffu, x, off);
        if (lane >= off) x += y;
    }
    if (lane == 31) wsum[warp] = x;
    __syncthreads();
    if (warp == 0) {
        int s = wsum[lane];
        #pragma unroll
        for (int off = 1; off < 32; off <<= 1) {
            int y = __shfl_up_sync(0xffffffffu, s, off);
            if (lane >= off) s += y;
        }
        wsum[lane] = s;
    }
    __syncthreads();
    int incl = x + ((warp > 0) ? wsum[warp - 1] : 0);
    if (t == SCAN_B - 1) s_total = incl;
    __syncthreads();

    if (t == 0) {
        int total = s_total;
        if (bid == 0) {
            g_ss.inc[0] = total;
            __threadfence();
            atomicExch(&g_ss.flag[0], 2);
            s_prefix = 0;
        } else {
            g_ss.agg[bid] = total;
            __threadfence();
            atomicExch(&g_ss.flag[bid], 1);
            int pfx = 0;
            for (int j = bid - 1; j >= 0; j--) {
                int f;
                do { f = atomicAdd(&g_ss.flag[j], 0); } while (f == 0);
                if (f == 2) { pfx += atomicAdd(&g_ss.inc[j], 0); break; }
                pfx += atomicAdd(&g_ss.agg[j], 0);
            }
            s_prefix = pfx;
            g_ss.inc[bid] = pfx + total;
            __threadfence();
            atomicExch(&g_ss.flag[bid], 2);
        }
    }
    __syncthreads();
    if (i < NP) g_offs[i] = s_prefix + incl - v;
}

// ---------------------------------------------------------------------------
// Fill: 4 edges/thread; the 4 atomics are issued before the 4 dependent
// stores (MLP vs L2-atomic latency). One atomic + one STG.64 per edge
// (offs-shift trick; node kernel compensates).
// ---------------------------------------------------------------------------
__global__ void fill_kernel(const int* __restrict__ src,
                            const int* __restrict__ dst,
                            const float* __restrict__ ew, int E) {
    int i4 = blockIdx.x * blockDim.x + threadIdx.x;
    int E4 = E >> 2;
    if (i4 < E4) {
        int4   s = ((const int4*)src)[i4];
        int4   d = ((const int4*)dst)[i4];
        float4 w = ((const float4*)ew)[i4];
        int i0 = atomicAdd(&g_offs[s.x], 1);
        int i1 = atomicAdd(&g_offs[s.y], 1);
        int i2 = atomicAdd(&g_offs[s.z], 1);
        int i3 = atomicAdd(&g_offs[s.w], 1);
        g_csr[i0] = make_int2(d.x, __float_as_int(w.x));
        g_csr[i1] = make_int2(d.y, __float_as_int(w.y));
        g_csr[i2] = make_int2(d.z, __float_as_int(w.z));
        g_csr[i3] = make_int2(d.w, __float_as_int(w.w));
    }
    if (i4 == 0) {
        for (int e = E4 << 2; e < E; e++) {
            int idx = atomicAdd(&g_offs[src[e]], 1);
            g_csr[idx] = make_int2(dst[e], __float_as_int(ew[e]));
        }
    }
}

// ---------------------------------------------------------------------------
// Node kernel: one warp per node, fp16 gather, fp32 accumulate, bias+ReLU.
// After fill, g_offs[i] = end of segment i (shifted).
// ---------------------------------------------------------------------------
__global__ void node_kernel(const float* __restrict__ b,
                            float* __restrict__ out, int N) {
    int node = (int)((blockIdx.x * (size_t)blockDim.x + threadIdx.x) >> 5);
    int lane = threadIdx.x & 31;
    if (node >= N) return;

    int beg = (node == 0) ? 0 : g_offs[node - 1];
    int end = g_offs[node];

    float4 acc = make_float4(0.f, 0.f, 0.f, 0.f);
    int i = beg;
    for (; i + 4 <= end; i += 4) {
        int2 p0 = g_csr[i],   p1 = g_csr[i+1];
        int2 p2 = g_csr[i+2], p3 = g_csr[i+3];
        float w0 = __int_as_float(p0.y), w1 = __int_as_float(p1.y);
        float w2 = __int_as_float(p2.y), w3 = __int_as_float(p3.y);
        uint2 u0 = ((const uint2*)(g_X0h + (size_t)p0.x * D))[lane];
        uint2 u1 = ((const uint2*)(g_X0h + (size_t)p1.x * D))[lane];
        uint2 u2 = ((const uint2*)(g_X0h + (size_t)p2.x * D))[lane];
        uint2 u3 = ((const uint2*)(g_X0h + (size_t)p3.x * D))[lane];
        float2 a, c;
        a = __half22float2(*(half2*)&u0.x); c = __half22float2(*(half2*)&u0.y);
        acc.x += w0*a.x; acc.y += w0*a.y; acc.z += w0*c.x; acc.w += w0*c.y;
        a = __half22float2(*(half2*)&u1.x); c = __half22float2(*(half2*)&u1.y);
        acc.x += w1*a.x; acc.y += w1*a.y; acc.z += w1*c.x; acc.w += w1*c.y;
        a = __half22float2(*(half2*)&u2.x); c = __half22float2(*(half2*)&u2.y);
        acc.x += w2*a.x; acc.y += w2*a.y; acc.z += w2*c.x; acc.w += w2*c.y;
        a = __half22float2(*(half2*)&u3.x); c = __half22float2(*(half2*)&u3.y);
        acc.x += w3*a.x; acc.y += w3*a.y; acc.z += w3*c.x; acc.w += w3*c.y;
    }
    for (; i < end; i++) {
        int2 p = g_csr[i];
        float wg = __int_as_float(p.y);
        uint2 u = ((const uint2*)(g_X0h + (size_t)p.x * D))[lane];
        float2 a = __half22float2(*(half2*)&u.x);
        float2 c = __half22float2(*(half2*)&u.y);
        acc.x += wg*a.x; acc.y += wg*a.y; acc.z += wg*c.x; acc.w += wg*c.y;
    }

    float4 bv = ((const float4*)b)[lane];
    acc.x = fmaxf(acc.x + bv.x, 0.f);
    acc.y = fmaxf(acc.y + bv.y, 0.f);
    acc.z = fmaxf(acc.z + bv.z, 0.f);
    acc.w = fmaxf(acc.w + bv.w, 0.f);
    ((float4*)(out + (size_t)node * D))[lane] = acc;
}

extern "C" void kernel_launch(void* const* d_in, const int* in_sizes, int n_in,
                              void* d_out, int out_size) {
    const float* notes = (const float*)d_in[0];
    const float* w     = (const float*)d_in[1];
    const float* b     = (const float*)d_in[2];
    const int*   esrc  = (const int*)d_in[3];
    const int*   edst  = (const int*)d_in[4];
    const float* ew    = (const float*)d_in[5];
    float*       out   = (float*)d_out;

    const int N = in_sizes[0] / D;          // 100000
    const int E = in_sizes[3];              // 1600000
    const int out_rows = out_size / D;      // 120000
    const int garment  = 2 * N - out_rows;  // 80000

    static void* ss_ptr = nullptr;
    if (!ss_ptr) cudaGetSymbolAddress(&ss_ptr, g_ss);

    // Zero scan scratch (single memset graph node), then w-fragment prep
    cudaMemsetAsync(ss_ptr, 0, sizeof(ScanScratch), 0);
    prep_kernel<<<16, 256>>>(w);

    // Fused tensor-core GEMM (2x2 warp tiles) + degree count (tail blocks)
    const int smem_bytes = 64 * SN_PITCH * 4 + 4096 * 16;   // 99,328 B
    cudaFuncSetAttribute(gemm_count_kernel,
                         cudaFuncAttributeMaxDynamicSharedMemorySize, smem_bytes);
    gemm_count_kernel<<<GEMM_BLOCKS + CNT_BLOCKS, 128, smem_bytes>>>(
        notes, esrc, out, N, garment, E);

    // Offsets (single-pass lookback scan)
    scan_kernel<<<NBLK, SCAN_B>>>();

    // CSR fill
    fill_kernel<<<((E >> 2) + 255) / 256, 256>>>(esrc, edst, ew, E);

    // Gather-only aggregation, fp16 messages, fused bias + ReLU
    node_kernel<<<(N + 7) / 8, 256>>>(b, out, N);
}

// round 10
// speedup vs baseline: 1.1107x; 1.1107x over previous
#include <cuda_runtime.h>
#include <cuda_fp16.h>

#define D      128
#define NMAX   100000
#define EMAX   1600000
#define CAP    64                             // bucket capacity (Poisson(16) max)

#define GEMM_BLOCKS ((NMAX + 63) / 64)        // 1563 (64-row tiles, 2 blk/SM)

// Scratch (device globals — no allocations allowed)
__device__ __half g_X0h[(size_t)NMAX * D];    // notes @ w in fp16 (25.6 MB)
__device__ uint4  g_wfrag[8 * 16 * 32];       // B fragments: {bh0,bh1,bl0,bl1}
__device__ int    g_deg[NMAX];                // per-node fill cursor / degree
__device__ int2   g_bucket[(size_t)NMAX * CAP];  // {dst, w_bits} buckets (51.2 MB)

static __device__ __forceinline__ unsigned pack_bf16x2(float f0, float f1) {
    unsigned h;
    asm("cvt.rn.bf16x2.f32 %0, %1, %2;" : "=r"(h) : "f"(f1), "f"(f0));
    return h;
}

// ---------------------------------------------------------------------------
// Prep: build w fragments in mma register order (16 blocks, tiny).
// ---------------------------------------------------------------------------
__global__ void prep_kernel(const float* __restrict__ w) {
    int f = blockIdx.x * 256 + threadIdx.x;   // 0..4095
    int lane = f & 31;
    int nt   = (f >> 5) & 15;
    int ks   = f >> 9;
    int g  = lane >> 2;
    int tq = lane & 3;
    int n  = nt * 8 + g;
    int k0 = ks * 16 + 2 * tq;
    int k1 = k0 + 8;

    float a0 = w[(k0)     * D + n];
    float a1 = w[(k0 + 1) * D + n];
    float c0 = w[(k1)     * D + n];
    float c1 = w[(k1 + 1) * D + n];

    unsigned bh0 = pack_bf16x2(a0, a1);
    unsigned bh1 = pack_bf16x2(c0, c1);
    float h0 = __uint_as_float(bh0 << 16);
    float h1 = __uint_as_float(bh0 & 0xffff0000u);
    float h2 = __uint_as_float(bh1 << 16);
    float h3 = __uint_as_float(bh1 & 0xffff0000u);
    unsigned bl0 = pack_bf16x2(a0 - h0, a1 - h1);
    unsigned bl1 = pack_bf16x2(c0 - h2, c1 - h3);

    g_wfrag[f] = make_uint4(bh0, bh1, bl0, bl1);
}

// ---------------------------------------------------------------------------
// Fused fill + tensor-core GEMM.
// Blocks [0, fillBlocks): bucket fill — one atomic slot-claim + one STG.64
// per edge, interleaved (the measured-fastest pattern). Tiny 0-smem blocks
// that drain in the leading waves and overlap gemm staging.
// Blocks [fillBlocks, +GEMM_BLOCKS): R7's proven 1x-tiled bf16 MMA GEMM
// (64 rows x 128 cols, 4 warps, nt=16; 99 KB smem -> 2 blocks/SM).
// ---------------------------------------------------------------------------
#define SN_PITCH 132

__global__ void __launch_bounds__(128) gemm_fill_kernel(
        const float* __restrict__ notes,
        const int*   __restrict__ esrc,
        const int*   __restrict__ edst,
        const float* __restrict__ ew,
        float* __restrict__ out, int N, int garment, int E, int fillBlocks) {
    if (blockIdx.x < fillBlocks) {
        // ---- bucket fill path ----
        int i4 = blockIdx.x * 128 + threadIdx.x;
        int E4 = E >> 2;
        if (i4 < E4) {
            int4   s = ((const int4*)esrc)[i4];
            int4   d = ((const int4*)edst)[i4];
            float4 w = ((const float4*)ew)[i4];
            int slot;
            slot = atomicAdd(&g_deg[s.x], 1);
            g_bucket[(size_t)s.x * CAP + slot] = make_int2(d.x, __float_as_int(w.x));
            slot = atomicAdd(&g_deg[s.y], 1);
            g_bucket[(size_t)s.y * CAP + slot] = make_int2(d.y, __float_as_int(w.y));
            slot = atomicAdd(&g_deg[s.z], 1);
            g_bucket[(size_t)s.z * CAP + slot] = make_int2(d.z, __float_as_int(w.z));
            slot = atomicAdd(&g_deg[s.w], 1);
            g_bucket[(size_t)s.w * CAP + slot] = make_int2(d.w, __float_as_int(w.w));
        }
        if (i4 == 0) {
            for (int e = E4 << 2; e < E; e++) {
                int s = esrc[e];
                int slot = atomicAdd(&g_deg[s], 1);
                g_bucket[(size_t)s * CAP + slot] = make_int2(edst[e], __float_as_int(ew[e]));
            }
        }
        return;
    }

    extern __shared__ char smem_raw[];
    float* s_n  = (float*)smem_raw;                           // [64][132] f32
    uint4* s_bf = (uint4*)(smem_raw + 64 * SN_PITCH * 4);     // [8*16*32]

    const int t    = threadIdx.x;
    const int warp = t >> 5;
    const int lane = t & 31;
    const int g    = lane >> 2;
    const int tq   = lane & 3;
    const int row0 = (blockIdx.x - fillBlocks) * 64;

    #pragma unroll
    for (int i = t; i < 4096; i += 128) s_bf[i] = g_wfrag[i];

    const float4* n4 = (const float4*)notes;
    #pragma unroll
    for (int i = t; i < 2048; i += 128) {
        int r = i >> 5, c4 = i & 31;
        int gr = row0 + r;
        float4 v = make_float4(0.f, 0.f, 0.f, 0.f);
        if (gr < N) v = n4[(size_t)gr * 32 + c4];
        *(float4*)&s_n[r * SN_PITCH + c4 * 4] = v;
    }
    __syncthreads();

    float acc[16][4];
    #pragma unroll
    for (int nt = 0; nt < 16; nt++)
        #pragma unroll
        for (int j = 0; j < 4; j++) acc[nt][j] = 0.f;

    const int arow = warp * 16 + g;

    #pragma unroll
    for (int ks = 0; ks < 8; ks++) {
        unsigned ahi[4], alo[4];
        #pragma unroll
        for (int i = 0; i < 4; i++) {
            int r = arow + (i & 1) * 8;
            int k = ks * 16 + tq * 2 + (i >> 1) * 8;
            float2 f = *(const float2*)&s_n[r * SN_PITCH + k];
            unsigned h = pack_bf16x2(f.x, f.y);
            float hx = __uint_as_float(h << 16);
            float hy = __uint_as_float(h & 0xffff0000u);
            ahi[i] = h;
            alo[i] = pack_bf16x2(f.x - hx, f.y - hy);
        }
        const uint4* bf = &s_bf[ks * 16 * 32 + lane];
        #pragma unroll
        for (int nt = 0; nt < 16; nt++) {
            uint4 f = bf[nt * 32];
            asm volatile(
                "mma.sync.aligned.m16n8k16.row.col.f32.bf16.bf16.f32 "
                "{%0,%1,%2,%3}, {%4,%5,%6,%7}, {%8,%9}, {%0,%1,%2,%3};"
                : "+f"(acc[nt][0]), "+f"(acc[nt][1]), "+f"(acc[nt][2]), "+f"(acc[nt][3])
                : "r"(ahi[0]), "r"(ahi[1]), "r"(ahi[2]), "r"(ahi[3]),
                  "r"(f.x), "r"(f.y));
            asm volatile(
                "mma.sync.aligned.m16n8k16.row.col.f32.bf16.bf16.f32 "
                "{%0,%1,%2,%3}, {%4,%5,%6,%7}, {%8,%9}, {%0,%1,%2,%3};"
                : "+f"(acc[nt][0]), "+f"(acc[nt][1]), "+f"(acc[nt][2]), "+f"(acc[nt][3])
                : "r"(ahi[0]), "r"(ahi[1]), "r"(ahi[2]), "r"(ahi[3]),
                  "r"(f.z), "r"(f.w));
            asm volatile(
                "mma.sync.aligned.m16n8k16.row.col.f32.bf16.bf16.f32 "
                "{%0,%1,%2,%3}, {%4,%5,%6,%7}, {%8,%9}, {%0,%1,%2,%3};"
                : "+f"(acc[nt][0]), "+f"(acc[nt][1]), "+f"(acc[nt][2]), "+f"(acc[nt][3])
                : "r"(alo[0]), "r"(alo[1]), "r"(alo[2]), "r"(alo[3]),
                  "r"(f.x), "r"(f.y));
        }
    }

    // Epilogue: X0 -> fp16 scratch; rows >= garment -> fp32 output tail.
    const int r0 = row0 + arow;
    const int r1 = r0 + 8;
    #pragma unroll
    for (int nt = 0; nt < 16; nt++) {
        int col = nt * 8 + tq * 2;
        if (r0 < N) {
            *(half2*)&g_X0h[(size_t)r0 * D + col] = __floats2half2_rn(acc[nt][0], acc[nt][1]);
            if (r0 >= garment)
                *(float2*)&out[(size_t)(N + r0 - garment) * D + col] =
                    make_float2(acc[nt][0], acc[nt][1]);
        }
        if (r1 < N) {
            *(half2*)&g_X0h[(size_t)r1 * D + col] = __floats2half2_rn(acc[nt][2], acc[nt][3]);
            if (r1 >= garment)
                *(float2*)&out[(size_t)(N + r1 - garment) * D + col] =
                    make_float2(acc[nt][2], acc[nt][3]);
        }
    }
}

// ---------------------------------------------------------------------------
// Node kernel: one warp per node, bucket gather, fp16 messages, fp32
// accumulate, fused bias+ReLU.
// ---------------------------------------------------------------------------
__global__ void node_kernel(const float* __restrict__ b,
                            float* __restrict__ out, int N) {
    int node = (int)((blockIdx.x * (size_t)blockDim.x + threadIdx.x) >> 5);
    int lane = threadIdx.x & 31;
    if (node >= N) return;

    const int2* bucket = &g_bucket[(size_t)node * CAP];
    int cnt = g_deg[node];

    float4 acc = make_float4(0.f, 0.f, 0.f, 0.f);
    int i = 0;
    for (; i + 4 <= cnt; i += 4) {
        int2 p0 = bucket[i],   p1 = bucket[i+1];
        int2 p2 = bucket[i+2], p3 = bucket[i+3];
        float w0 = __int_as_float(p0.y), w1 = __int_as_float(p1.y);
        float w2 = __int_as_float(p2.y), w3 = __int_as_float(p3.y);
        uint2 u0 = ((const uint2*)(g_X0h + (size_t)p0.x * D))[lane];
        uint2 u1 = ((const uint2*)(g_X0h + (size_t)p1.x * D))[lane];
        uint2 u2 = ((const uint2*)(g_X0h + (size_t)p2.x * D))[lane];
        uint2 u3 = ((const uint2*)(g_X0h + (size_t)p3.x * D))[lane];
        float2 a, c;
        a = __half22float2(*(half2*)&u0.x); c = __half22float2(*(half2*)&u0.y);
        acc.x += w0*a.x; acc.y += w0*a.y; acc.z += w0*c.x; acc.w += w0*c.y;
        a = __half22float2(*(half2*)&u1.x); c = __half22float2(*(half2*)&u1.y);
        acc.x += w1*a.x; acc.y += w1*a.y; acc.z += w1*c.x; acc.w += w1*c.y;
        a = __half22float2(*(half2*)&u2.x); c = __half22float2(*(half2*)&u2.y);
        acc.x += w2*a.x; acc.y += w2*a.y; acc.z += w2*c.x; acc.w += w2*c.y;
        a = __half22float2(*(half2*)&u3.x); c = __half22float2(*(half2*)&u3.y);
        acc.x += w3*a.x; acc.y += w3*a.y; acc.z += w3*c.x; acc.w += w3*c.y;
    }
    for (; i < cnt; i++) {
        int2 p = bucket[i];
        float wg = __int_as_float(p.y);
        uint2 u = ((const uint2*)(g_X0h + (size_t)p.x * D))[lane];
        float2 a = __half22float2(*(half2*)&u.x);
        float2 c = __half22float2(*(half2*)&u.y);
        acc.x += wg*a.x; acc.y += wg*a.y; acc.z += wg*c.x; acc.w += wg*c.y;
    }

    float4 bv = ((const float4*)b)[lane];
    acc.x = fmaxf(acc.x + bv.x, 0.f);
    acc.y = fmaxf(acc.y + bv.y, 0.f);
    acc.z = fmaxf(acc.z + bv.z, 0.f);
    acc.w = fmaxf(acc.w + bv.w, 0.f);
    ((float4*)(out + (size_t)node * D))[lane] = acc;
}

extern "C" void kernel_launch(void* const* d_in, const int* in_sizes, int n_in,
                              void* d_out, int out_size) {
    const float* notes = (const float*)d_in[0];
    const float* w     = (const float*)d_in[1];
    const float* b     = (const float*)d_in[2];
    const int*   esrc  = (const int*)d_in[3];
    const int*   edst  = (const int*)d_in[4];
    const float* ew    = (const float*)d_in[5];
    float*       out   = (float*)d_out;

    const int N = in_sizes[0] / D;          // 100000
    const int E = in_sizes[3];              // 1600000
    const int out_rows = out_size / D;      // 120000
    const int garment  = 2 * N - out_rows;  // 80000

    static void* deg_ptr = nullptr;
    if (!deg_ptr) cudaGetSymbolAddress(&deg_ptr, g_deg);

    // Zero per-node cursors (single memset graph node, 400 KB)
    cudaMemsetAsync(deg_ptr, 0, NMAX * sizeof(int), 0);

    // w-fragment prep
    prep_kernel<<<16, 256>>>(w);

    // Fused bucket fill (leading blocks) + tensor-core GEMM
    const int fillBlocks = ((E >> 2) + 127) / 128;            // 3125
    const int smem_bytes = 64 * SN_PITCH * 4 + 4096 * 16;     // 99,328 B
    cudaFuncSetAttribute(gemm_fill_kernel,
                         cudaFuncAttributeMaxDynamicSharedMemorySize, smem_bytes);
    gemm_fill_kernel<<<fillBlocks + GEMM_BLOCKS, 128, smem_bytes>>>(
        notes, esrc, edst, ew, out, N, garment, E, fillBlocks);

    // Gather-only aggregation, fp16 messages, fused bias + ReLU
    node_kernel<<<(N + 7) / 8, 256>>>(b, out, N);
}

// round 11
// speedup vs baseline: 1.1449x; 1.0308x over previous
#include <cuda_runtime.h>
#include <cuda_fp16.h>

#define D      128
#define NMAX   100000
#define EMAX   1600000
#define CAP    64                             // bucket capacity (Poisson(16) max)

#define GEMM_BLOCKS ((NMAX + 63) / 64)        // 1563 (64-row tiles)

// Scratch (device globals — no allocations allowed)
__device__ __half g_X0h[(size_t)NMAX * D];    // notes @ w in fp16 (25.6 MB)
__device__ uint4  g_wfrag[8 * 16 * 32];       // B fragments: {bh0,bh1,bl0,bl1}
__device__ int    g_deg[NMAX];                // per-node fill cursor / degree
__device__ int2   g_bucket[(size_t)NMAX * CAP];  // {dst, w_bits} buckets (51.2 MB)

static __device__ __forceinline__ unsigned pack_bf16x2(float f0, float f1) {
    unsigned h;
    asm("cvt.rn.bf16x2.f32 %0, %1, %2;" : "=r"(h) : "f"(f1), "f"(f0));
    return h;
}

// ---------------------------------------------------------------------------
// Prep: build w fragments in mma register order (16 blocks, tiny).
// ---------------------------------------------------------------------------
__global__ void prep_kernel(const float* __restrict__ w) {
    int f = blockIdx.x * 256 + threadIdx.x;   // 0..4095
    int lane = f & 31;
    int nt   = (f >> 5) & 15;
    int ks   = f >> 9;
    int g  = lane >> 2;
    int tq = lane & 3;
    int n  = nt * 8 + g;
    int k0 = ks * 16 + 2 * tq;
    int k1 = k0 + 8;

    float a0 = w[(k0)     * D + n];
    float a1 = w[(k0 + 1) * D + n];
    float c0 = w[(k1)     * D + n];
    float c1 = w[(k1 + 1) * D + n];

    unsigned bh0 = pack_bf16x2(a0, a1);
    unsigned bh1 = pack_bf16x2(c0, c1);
    float h0 = __uint_as_float(bh0 << 16);
    float h1 = __uint_as_float(bh0 & 0xffff0000u);
    float h2 = __uint_as_float(bh1 << 16);
    float h3 = __uint_as_float(bh1 & 0xffff0000u);
    unsigned bl0 = pack_bf16x2(a0 - h0, a1 - h1);
    unsigned bl1 = pack_bf16x2(c0 - h2, c1 - h3);

    g_wfrag[f] = make_uint4(bh0, bh1, bl0, bl1);
}

// ---------------------------------------------------------------------------
// Fused fill + tensor-core GEMM.
// Fill blocks: bucket fill (one atomic slot-claim + one STG.64 per edge).
// GEMM blocks: 64 rows x 128 cols, 4 warps. B fragments are read DIRECTLY
// from g_wfrag via __ldg — all blocks share the same 64 KB table, so it
// lives in L1/L2; smem holds only the A tile (33 KB) -> 4 blocks/SM
// (reg-limited), double the warps of the smem-staged version.
// ---------------------------------------------------------------------------
#define SN_PITCH 132

__global__ void __launch_bounds__(128) gemm_fill_kernel(
        const float* __restrict__ notes,
        const int*   __restrict__ esrc,
        const int*   __restrict__ edst,
        const float* __restrict__ ew,
        float* __restrict__ out, int N, int garment, int E, int fillBlocks) {
    if (blockIdx.x < fillBlocks) {
        // ---- bucket fill path ----
        int i4 = blockIdx.x * 128 + threadIdx.x;
        int E4 = E >> 2;
        if (i4 < E4) {
            int4   s = ((const int4*)esrc)[i4];
            int4   d = ((const int4*)edst)[i4];
            float4 w = ((const float4*)ew)[i4];
            int slot;
            slot = atomicAdd(&g_deg[s.x], 1);
            g_bucket[(size_t)s.x * CAP + slot] = make_int2(d.x, __float_as_int(w.x));
            slot = atomicAdd(&g_deg[s.y], 1);
            g_bucket[(size_t)s.y * CAP + slot] = make_int2(d.y, __float_as_int(w.y));
            slot = atomicAdd(&g_deg[s.z], 1);
            g_bucket[(size_t)s.z * CAP + slot] = make_int2(d.z, __float_as_int(w.z));
            slot = atomicAdd(&g_deg[s.w], 1);
            g_bucket[(size_t)s.w * CAP + slot] = make_int2(d.w, __float_as_int(w.w));
        }
        if (i4 == 0) {
            for (int e = E4 << 2; e < E; e++) {
                int s = esrc[e];
                int slot = atomicAdd(&g_deg[s], 1);
                g_bucket[(size_t)s * CAP + slot] = make_int2(edst[e], __float_as_int(ew[e]));
            }
        }
        return;
    }

    extern __shared__ char smem_raw[];
    float* s_n = (float*)smem_raw;                            // [64][132] f32

    const int t    = threadIdx.x;
    const int warp = t >> 5;
    const int lane = t & 31;
    const int g    = lane >> 2;
    const int tq   = lane & 3;
    const int row0 = (blockIdx.x - fillBlocks) * 64;

    // Stage notes tile only (64 x 128 f32), zero-fill OOB rows
    const float4* n4 = (const float4*)notes;
    #pragma unroll
    for (int i = t; i < 2048; i += 128) {
        int r = i >> 5, c4 = i & 31;
        int gr = row0 + r;
        float4 v = make_float4(0.f, 0.f, 0.f, 0.f);
        if (gr < N) v = n4[(size_t)gr * 32 + c4];
        *(float4*)&s_n[r * SN_PITCH + c4 * 4] = v;
    }
    __syncthreads();

    float acc[16][4];
    #pragma unroll
    for (int nt = 0; nt < 16; nt++)
        #pragma unroll
        for (int j = 0; j < 4; j++) acc[nt][j] = 0.f;

    const int arow = warp * 16 + g;

    #pragma unroll
    for (int ks = 0; ks < 8; ks++) {
        // A fragments: f32 -> bf16 hi/lo split on the fly
        unsigned ahi[4], alo[4];
        #pragma unroll
        for (int i = 0; i < 4; i++) {
            int r = arow + (i & 1) * 8;
            int k = ks * 16 + tq * 2 + (i >> 1) * 8;
            float2 f = *(const float2*)&s_n[r * SN_PITCH + k];
            unsigned h = pack_bf16x2(f.x, f.y);
            float hx = __uint_as_float(h << 16);
            float hy = __uint_as_float(h & 0xffff0000u);
            ahi[i] = h;
            alo[i] = pack_bf16x2(f.x - hx, f.y - hy);
        }
        // B fragments straight from the shared L1/L2-resident table
        const uint4* bf = &g_wfrag[ks * 16 * 32 + lane];
        #pragma unroll
        for (int nt = 0; nt < 16; nt++) {
            uint4 f = __ldg(&bf[nt * 32]);
            asm volatile(
                "mma.sync.aligned.m16n8k16.row.col.f32.bf16.bf16.f32 "
                "{%0,%1,%2,%3}, {%4,%5,%6,%7}, {%8,%9}, {%0,%1,%2,%3};"
                : "+f"(acc[nt][0]), "+f"(acc[nt][1]), "+f"(acc[nt][2]), "+f"(acc[nt][3])
                : "r"(ahi[0]), "r"(ahi[1]), "r"(ahi[2]), "r"(ahi[3]),
                  "r"(f.x), "r"(f.y));
            asm volatile(
                "mma.sync.aligned.m16n8k16.row.col.f32.bf16.bf16.f32 "
                "{%0,%1,%2,%3}, {%4,%5,%6,%7}, {%8,%9}, {%0,%1,%2,%3};"
                : "+f"(acc[nt][0]), "+f"(acc[nt][1]), "+f"(acc[nt][2]), "+f"(acc[nt][3])
                : "r"(ahi[0]), "r"(ahi[1]), "r"(ahi[2]), "r"(ahi[3]),
                  "r"(f.z), "r"(f.w));
            asm volatile(
                "mma.sync.aligned.m16n8k16.row.col.f32.bf16.bf16.f32 "
                "{%0,%1,%2,%3}, {%4,%5,%6,%7}, {%8,%9}, {%0,%1,%2,%3};"
                : "+f"(acc[nt][0]), "+f"(acc[nt][1]), "+f"(acc[nt][2]), "+f"(acc[nt][3])
                : "r"(alo[0]), "r"(alo[1]), "r"(alo[2]), "r"(alo[3]),
                  "r"(f.x), "r"(f.y));
        }
    }

    // Epilogue: X0 -> fp16 scratch; rows >= garment -> fp32 output tail.
    const int r0 = row0 + arow;
    const int r1 = r0 + 8;
    #pragma unroll
    for (int nt = 0; nt < 16; nt++) {
        int col = nt * 8 + tq * 2;
        if (r0 < N) {
            *(half2*)&g_X0h[(size_t)r0 * D + col] = __floats2half2_rn(acc[nt][0], acc[nt][1]);
            if (r0 >= garment)
                *(float2*)&out[(size_t)(N + r0 - garment) * D + col] =
                    make_float2(acc[nt][0], acc[nt][1]);
        }
        if (r1 < N) {
            *(half2*)&g_X0h[(size_t)r1 * D + col] = __floats2half2_rn(acc[nt][2], acc[nt][3]);
            if (r1 >= garment)
                *(float2*)&out[(size_t)(N + r1 - garment) * D + col] =
                    make_float2(acc[nt][2], acc[nt][3]);
        }
    }
}

// ---------------------------------------------------------------------------
// Node kernel: one warp per node, bucket gather, fp16 messages, fp32
// accumulate, fused bias+ReLU.
// ---------------------------------------------------------------------------
__global__ void node_kernel(const float* __restrict__ b,
                            float* __restrict__ out, int N) {
    int node = (int)((blockIdx.x * (size_t)blockDim.x + threadIdx.x) >> 5);
    int lane = threadIdx.x & 31;
    if (node >= N) return;

    const int2* bucket = &g_bucket[(size_t)node * CAP];
    int cnt = g_deg[node];

    float4 acc = make_float4(0.f, 0.f, 0.f, 0.f);
    int i = 0;
    for (; i + 4 <= cnt; i += 4) {
        int2 p0 = bucket[i],   p1 = bucket[i+1];
        int2 p2 = bucket[i+2], p3 = bucket[i+3];
        float w0 = __int_as_float(p0.y), w1 = __int_as_float(p1.y);
        float w2 = __int_as_float(p2.y), w3 = __int_as_float(p3.y);
        uint2 u0 = ((const uint2*)(g_X0h + (size_t)p0.x * D))[lane];
        uint2 u1 = ((const uint2*)(g_X0h + (size_t)p1.x * D))[lane];
        uint2 u2 = ((const uint2*)(g_X0h + (size_t)p2.x * D))[lane];
        uint2 u3 = ((const uint2*)(g_X0h + (size_t)p3.x * D))[lane];
        float2 a, c;
        a = __half22float2(*(half2*)&u0.x); c = __half22float2(*(half2*)&u0.y);
        acc.x += w0*a.x; acc.y += w0*a.y; acc.z += w0*c.x; acc.w += w0*c.y;
        a = __half22float2(*(half2*)&u1.x); c = __half22float2(*(half2*)&u1.y);
        acc.x += w1*a.x; acc.y += w1*a.y; acc.z += w1*c.x; acc.w += w1*c.y;
        a = __half22float2(*(half2*)&u2.x); c = __half22float2(*(half2*)&u2.y);
        acc.x += w2*a.x; acc.y += w2*a.y; acc.z += w2*c.x; acc.w += w2*c.y;
        a = __half22float2(*(half2*)&u3.x); c = __half22float2(*(half2*)&u3.y);
        acc.x += w3*a.x; acc.y += w3*a.y; acc.z += w3*c.x; acc.w += w3*c.y;
    }
    for (; i < cnt; i++) {
        int2 p = bucket[i];
        float wg = __int_as_float(p.y);
        uint2 u = ((const uint2*)(g_X0h + (size_t)p.x * D))[lane];
        float2 a = __half22float2(*(half2*)&u.x);
        float2 c = __half22float2(*(half2*)&u.y);
        acc.x += wg*a.x; acc.y += wg*a.y; acc.z += wg*c.x; acc.w += wg*c.y;
    }

    float4 bv = ((const float4*)b)[lane];
    acc.x = fmaxf(acc.x + bv.x, 0.f);
    acc.y = fmaxf(acc.y + bv.y, 0.f);
    acc.z = fmaxf(acc.z + bv.z, 0.f);
    acc.w = fmaxf(acc.w + bv.w, 0.f);
    ((float4*)(out + (size_t)node * D))[lane] = acc;
}

extern "C" void kernel_launch(void* const* d_in, const int* in_sizes, int n_in,
                              void* d_out, int out_size) {
    const float* notes = (const float*)d_in[0];
    const float* w     = (const float*)d_in[1];
    const float* b     = (const float*)d_in[2];
    const int*   esrc  = (const int*)d_in[3];
    const int*   edst  = (const int*)d_in[4];
    const float* ew    = (const float*)d_in[5];
    float*       out   = (float*)d_out;

    const int N = in_sizes[0] / D;          // 100000
    const int E = in_sizes[3];              // 1600000
    const int out_rows = out_size / D;      // 120000
    const int garment  = 2 * N - out_rows;  // 80000

    static void* deg_ptr = nullptr;
    if (!deg_ptr) cudaGetSymbolAddress(&deg_ptr, g_deg);

    // Zero per-node cursors (single memset graph node, 400 KB)
    cudaMemsetAsync(deg_ptr, 0, NMAX * sizeof(int), 0);

    // w-fragment prep
    prep_kernel<<<16, 256>>>(w);

    // Fused bucket fill (leading blocks) + tensor-core GEMM (L2-resident B)
    const int fillBlocks = ((E >> 2) + 127) / 128;            // 3125
    const int smem_bytes = 64 * SN_PITCH * 4;                 // 33,792 B
    cudaFuncSetAttribute(gemm_fill_kernel,
                         cudaFuncAttributeMaxDynamicSharedMemorySize, smem_bytes);
    gemm_fill_kernel<<<fillBlocks + GEMM_BLOCKS, 128, smem_bytes>>>(
        notes, esrc, edst, ew, out, N, garment, E, fillBlocks);

    // Gather-only aggregation, fp16 messages, fused bias + ReLU
    node_kernel<<<(N + 7) / 8, 256>>>(b, out, N);
}